// round 11
// baseline (speedup 1.0000x reference)
#include <cuda_runtime.h>

#define NN 20000
#define NE 320000
#define SQRT3F 1.7320508075688772f
#define INV_NORM (1.0f/319999.0f)

typedef unsigned long long u64;

// ---------------- persistent device state (no allocs allowed) ----------------
__device__ __align__(16) float g_s[NN*16];      // node scalars
__device__ __align__(16) float g_v[NN*3];       // node vector (positions)
__device__ __align__(16) float g_accS[NN*16];   // aggregated scalar messages
__device__ __align__(16) float g_accV[NN*48];   // aggregated vector messages [16][3]
__device__ __align__(16) float g_accAv[NN*3];   // aggregated edge attr vectors
__device__ int g_cnt_i[NN];                     // per-receiver edge counts
__device__ int g_row[NN+1];                     // CSR row offsets (receiver-sorted)
__device__ int g_fill[NN];                      // scatter cursors
__device__ int g_src[NE];                       // senders in receiver-sorted order
__device__ int g_dst[NE];                       // receivers in receiver-sorted order

// ---------------- f32x2 packed-math helpers (sm_103a dual FMA pipe) ----------
__device__ __forceinline__ u64 pk2(float a, float b){ u64 r; asm("mov.b64 %0,{%1,%2};":"=l"(r):"f"(a),"f"(b)); return r; }
__device__ __forceinline__ u64 bc2(float a){ return pk2(a,a); }
__device__ __forceinline__ void upk2(u64 v, float&a, float&b){ asm("mov.b64 {%0,%1},%2;":"=f"(a),"=f"(b):"l"(v)); }
__device__ __forceinline__ void fma2_(u64&d, u64 a, u64 b){ asm("fma.rn.f32x2 %0,%1,%2,%0;":"+l"(d):"l"(a),"l"(b)); }
__device__ __forceinline__ u64 mul2_(u64 a, u64 b){ u64 r; asm("mul.rn.f32x2 %0,%1,%2;":"=l"(r):"l"(a),"l"(b)); return r; }

__device__ __forceinline__ float sigmoidf_(float x){
    return 1.0f/(1.0f+__expf(-x));
}
// jax.nn.gelu default (approximate=True)
__device__ __forceinline__ float geluf_(float x){
    float t = 0.7978845608028654f*(x + 0.044715f*x*x*x);
    float e = __expf(2.0f*t);
    float th = 1.0f - 2.0f/(e+1.0f);
    return 0.5f*x*(1.0f+th);
}

// ---------------- init / CSR build / zero / pack ----------------
__global__ void init_kernel(const float* __restrict__ s_in, const float* __restrict__ v_in){
    int i = blockIdx.x*256 + threadIdx.x;
    if (i < NN*16) g_s[i] = s_in[i];
    if (i < NN*3)  g_v[i] = v_in[i];
    if (i < NN)    g_cnt_i[i] = 0;
}

__global__ void count_kernel(const int* __restrict__ receivers){
    int e = blockIdx.x*256 + threadIdx.x;
    if (e < NE) atomicAdd(&g_cnt_i[receivers[e]], 1);
}

__global__ void scan_kernel(){
    __shared__ int part[1024];
    int t = threadIdx.x;
    int base = t*20;
    int s = 0;
    if (base < NN){
        #pragma unroll
        for (int i=0;i<20;i++){ int n=base+i; if (n<NN) s += g_cnt_i[n]; }
    }
    part[t]=s; __syncthreads();
    for (int off=1;off<1024;off<<=1){
        int v = (t>=off)?part[t-off]:0;
        __syncthreads();
        part[t]+=v;
        __syncthreads();
    }
    int excl = (t==0)?0:part[t-1];
    if (base < NN){
        int run = excl;
        #pragma unroll
        for (int i=0;i<20;i++){
            int n=base+i;
            if (n<NN){ g_row[n]=run; g_fill[n]=run; run+=g_cnt_i[n]; }
        }
    }
    if (t==1023) g_row[NN]=part[1023];
}

__global__ void scatter_kernel(const int* __restrict__ senders, const int* __restrict__ receivers){
    int e = blockIdx.x*256 + threadIdx.x;
    if (e >= NE) return;
    int ri = receivers[e];
    int s = atomicAdd(&g_fill[ri], 1);
    g_src[s] = senders[e];
    g_dst[s] = ri;
}

__global__ void zero_kernel(){
    int i = blockIdx.x*256 + threadIdx.x;
    if (i < NN*48) g_accV[i]  = 0.f;
    if (i < NN*16) g_accS[i]  = 0.f;
    if (i < NN*3)  g_accAv[i] = 0.f;
}

__global__ void pack_kernel(float* __restrict__ out){
    int n = blockIdx.x*256 + threadIdx.x;
    if (n >= NN) return;
    #pragma unroll
    for (int p=0;p<16;p++) out[n*19+p] = g_s[n*16+p];
    out[n*19+16] = g_v[n*3+0];
    out[n*19+17] = g_v[n*3+1];
    out[n*19+18] = g_v[n*3+2];
}

// ---------------- edge kernel: 2x TPLG + fused warp-segmented aggregation ----------------
// NE % 128 == 0 -> every thread holds a valid edge; full-warp shuffles are safe.
__global__ void __launch_bounds__(128) edge_kernel(
    const float* __restrict__ Ws0, const float* __restrict__ bs0, const float* __restrict__ Wv0,
    const float* __restrict__ Ws1, const float* __restrict__ bs1, const float* __restrict__ Wv1)
{
    __shared__ __align__(16) float sWs0[34*32];
    __shared__ __align__(16) float sWv0[34*16];
    __shared__ __align__(16) float sWs1[32*32];
    __shared__ __align__(16) float sWv1[32*16];
    __shared__ __align__(16) float sbs0[32];
    __shared__ __align__(16) float sbs1[32];
    int tid = threadIdx.x;
    for (int i=tid;i<34*32;i+=128) sWs0[i]=Ws0[i];
    for (int i=tid;i<34*16;i+=128) sWv0[i]=Wv0[i];
    for (int i=tid;i<32*32;i+=128) sWs1[i]=Ws1[i];
    for (int i=tid;i<32*16;i+=128) sWv1[i]=Wv1[i];
    if (tid<32){ sbs0[tid]=bs0[tid]; sbs1[tid]=bs1[tid]; }
    __syncthreads();

    int s = blockIdx.x*128 + tid;      // slot in receiver-sorted order
    int si = g_src[s], ri = g_dst[s];

    float vsx=g_v[si*3+0], vsy=g_v[si*3+1], vsz=g_v[si*3+2];
    float vrx=g_v[ri*3+0], vry=g_v[ri*3+1], vrz=g_v[ri*3+2];
    float rx=vsx-vrx, ry=vsy-vry, rz=vsz-vrz;
    float nrm = sqrtf(rx*rx+ry*ry+rz*rz) + 1e-8f;
    float kk0 = SQRT3F/nrm;
    float avx=kk0*rx, avy=kk0*ry, avz=kk0*rz;   // a_v = sqrt(3) * rhat

    float xs[32];
    {
        const float4* s4a = (const float4*)(g_s + si*16);
        const float4* s4b = (const float4*)(g_s + ri*16);
        #pragma unroll
        for (int j=0;j<4;j++){ float4 t=s4a[j]; xs[4*j]=t.x; xs[4*j+1]=t.y; xs[4*j+2]=t.z; xs[4*j+3]=t.w; }
        #pragma unroll
        for (int j=0;j<4;j++){ float4 t=s4b[j]; xs[16+4*j]=t.x; xs[16+4*j+1]=t.y; xs[16+4*j+2]=t.z; xs[16+4*j+3]=t.w; }
    }
    float dS = vsx*avx+vsy*avy+vsz*avz;
    float dR = vrx*avx+vry*avy+vrz*avz;

    // ---- layer 1 (packed q-pairs) ----
    u64 sl2[16], ua[8];
    {
        u64 dS2 = bc2(dS), dR2 = bc2(dR);
        const u64* b0  = (const u64*)sbs0;
        const u64* w32 = (const u64*)(sWs0 + 32*32);
        const u64* w33 = (const u64*)(sWs0 + 33*32);
        #pragma unroll
        for (int k=0;k<16;k++){ sl2[k]=b0[k]; fma2_(sl2[k],dS2,w32[k]); fma2_(sl2[k],dR2,w33[k]); }
        #pragma unroll
        for (int k=0;k<8;k++) ua[k]=0ull;
    }
    #pragma unroll 4
    for (int a=0;a<32;a++){
        u64 xa2 = bc2(xs[a]);
        const u64* w = (const u64*)(sWs0 + a*32);
        #pragma unroll
        for (int k=0;k<16;k++) fma2_(sl2[k], xa2, w[k]);
        const u64* v = (const u64*)(sWv0 + a*16);
        #pragma unroll
        for (int k=0;k<8;k++) fma2_(ua[k], xa2, v[k]);
    }
    float sl[32], u[16];
    #pragma unroll
    for (int k=0;k<16;k++) upk2(sl2[k], sl[2*k], sl[2*k+1]);
    #pragma unroll
    for (int k=0;k<8;k++)  upk2(ua[k], u[2*k], u[2*k+1]);

    float ms[16], mvx[16], mvy[16], mvz[16];
    #pragma unroll
    for (int q=0;q<16;q++){
        float g   = sigmoidf_(sl[q]);
        float w32 = sWv0[32*16+q], w33 = sWv0[33*16+q];
        mvx[q] = (avx*u[q] + vsx*w32 + vrx*w33)*g;
        mvy[q] = (avy*u[q] + vsy*w32 + vry*w33)*g;
        mvz[q] = (avz*u[q] + vsz*w32 + vrz*w33)*g;
        ms[q]  = geluf_(sl[16+q]);
    }

    // ---- layer 2 (packed) ----
    u64 s22[16], u22[8];
    {
        const u64* b1 = (const u64*)sbs1;
        #pragma unroll
        for (int k=0;k<16;k++) s22[k]=b1[k];
        #pragma unroll
        for (int k=0;k<8;k++)  u22[k]=0ull;
    }
    #pragma unroll 2
    for (int p=0;p<16;p++){
        float m  = ms[p];
        float d2 = mvx[p]*avx + mvy[p]*avy + mvz[p]*avz;
        u64 m2 = bc2(m), dd = bc2(d2);
        const u64* w  = (const u64*)(sWs1 + p*32);
        const u64* wb = (const u64*)(sWs1 + (16+p)*32);
        #pragma unroll
        for (int k=0;k<16;k++){ fma2_(s22[k], m2, w[k]); fma2_(s22[k], dd, wb[k]); }
        const u64* v = (const u64*)(sWv1 + p*16);
        #pragma unroll
        for (int k=0;k<8;k++) fma2_(u22[k], m2, v[k]);
    }
    float s2[32];
    #pragma unroll
    for (int k=0;k<16;k++) upk2(s22[k], s2[2*k], s2[2*k+1]);

    // ---- vector output ----
    u64 vxa[8], vya[8], vza[8];
    {
        u64 ax2=bc2(avx), ay2=bc2(avy), az2=bc2(avz);
        #pragma unroll
        for (int k=0;k<8;k++){ vxa[k]=mul2_(ax2,u22[k]); vya[k]=mul2_(ay2,u22[k]); vza[k]=mul2_(az2,u22[k]); }
    }
    #pragma unroll 4
    for (int p=0;p<16;p++){
        u64 mx=bc2(mvx[p]), my=bc2(mvy[p]), mz=bc2(mvz[p]);
        const u64* w2 = (const u64*)(sWv1 + (16+p)*16);
        #pragma unroll
        for (int k=0;k<8;k++){ fma2_(vxa[k],mx,w2[k]); fma2_(vya[k],my,w2[k]); fma2_(vza[k],mz,w2[k]); }
    }

    // ---- stage the 67 outputs into a local array (channel-indexed) ----
    // layout: 0..15 = scalar msgs; 16..63 = vector msgs [q][xyz]; 64..66 = a_v
    float vals[67];
    #pragma unroll
    for (int k=0;k<8;k++){
        float g0 = sigmoidf_(s2[2*k]);
        float g1 = sigmoidf_(s2[2*k+1]);
        float x0,x1,y0,y1,z0,z1;
        upk2(vxa[k],x0,x1); upk2(vya[k],y0,y1); upk2(vza[k],z0,z1);
        vals[2*k]   = geluf_(s2[16+2*k]);
        vals[2*k+1] = geluf_(s2[16+2*k+1]);
        vals[16+(2*k)*3+0]   = x0*g0;
        vals[16+(2*k)*3+1]   = y0*g0;
        vals[16+(2*k)*3+2]   = z0*g0;
        vals[16+(2*k+1)*3+0] = x1*g1;
        vals[16+(2*k+1)*3+1] = y1*g1;
        vals[16+(2*k+1)*3+2] = z1*g1;
    }
    vals[64]=avx; vals[65]=avy; vals[66]=avz;

    // ---- fused aggregation: warp-segmented reduce + head-lane atomics (ONE code instance) ----
    int lane = tid & 31;
    const unsigned FULL = 0xffffffffu;
    int rup = __shfl_up_sync(FULL, ri, 1);
    bool head = (lane==0) || (rup != ri);
    bool ok1  = (lane<=30) && (__shfl_down_sync(FULL, ri, 1) ==ri);
    bool ok2  = (lane<=29) && (__shfl_down_sync(FULL, ri, 2) ==ri);
    bool ok4  = (lane<=27) && (__shfl_down_sync(FULL, ri, 4) ==ri);
    bool ok8  = (lane<=23) && (__shfl_down_sync(FULL, ri, 8) ==ri);
    bool ok16 = (lane<=15) && (__shfl_down_sync(FULL, ri, 16)==ri);

    float* accS  = g_accS  + ri*16;
    float* accV  = g_accV  + ri*48;
    float* accAv = g_accAv + ri*3;

    #pragma unroll 1
    for (int c=0;c<67;c++){
        float v = vals[c];
        float t;
        t = __shfl_down_sync(FULL, v, 1);  if (ok1)  v += t;
        t = __shfl_down_sync(FULL, v, 2);  if (ok2)  v += t;
        t = __shfl_down_sync(FULL, v, 4);  if (ok4)  v += t;
        t = __shfl_down_sync(FULL, v, 8);  if (ok8)  v += t;
        t = __shfl_down_sync(FULL, v, 16); if (ok16) v += t;
        if (head){
            float* addr = (c<16) ? (accS + c) : ((c<64) ? (accV + (c-16)) : (accAv + (c-64)));
            atomicAdd(addr, v);
        }
    }
}

// ---------------- node kernel: thread-pair per node, channel-split ----------------
__global__ void __launch_bounds__(256) node_kernel(
    const float* __restrict__ nWs, const float* __restrict__ nbs, const float* __restrict__ nWv,
    const float* __restrict__ fWs, const float* __restrict__ fbs, const float* __restrict__ fWv)
{
    __shared__ __align__(16) float sW[2*289*18];
    __shared__ __align__(16) float sV[2*289];
    __shared__ __align__(16) float sB[2*17];
    __shared__ __align__(16) float sF[256];
    __shared__ __align__(16) float sFb[16];
    __shared__ float sFv[1];
    int tid = threadIdx.x;
    for (int i=tid;i<2*289*17;i+=256){
        int b = i/(289*17); int r = i - b*289*17; int p = r/17; int q = r - p*17;
        sW[b*289*18 + p*18 + q] = nWs[i];
    }
    for (int i=tid;i<2*289;i+=256) sV[i]=nWv[i];
    if (tid<34) sB[tid]=nbs[tid];
    if (tid<256) sF[tid]=fWs[tid];
    if (tid<16) sFb[tid]=fbs[tid];
    if (tid==0) sFv[0]=fWv[0];
    __syncthreads();

    int id = blockIdx.x*256 + tid;
    bool valid = (id < 2*NN);
    int n  = valid ? (id >> 1) : (NN-1);   // clamp: ghost threads compute but never store
    int h  = id & 1;

    int r0i = g_row[n], r1i = g_row[n+1];
    float cnt = (float)(r1i - r0i);
    float fsc = INV_NORM / fmaxf(cnt,1.0f);
    float ys[17];
    #pragma unroll
    for (int c=0;c<16;c++) ys[c] = g_accS[n*16+c]*fsc;
    ys[16] = (cnt>0.f) ? INV_NORM : 0.f;

    float nsv[16];
    #pragma unroll
    for (int a=0;a<16;a++) nsv[a]=g_s[n*16+a];
    float nvx=g_v[n*3+0], nvy=g_v[n*3+1], nvz=g_v[n*3+2];

    int hoff = 8*h;

    #pragma unroll 1
    for (int b=0;b<2;b++){
        const float* Wb = sW + b*289*18;
        const float* Vb = sV + b*289;
        u64 sl2[4];
        float sl16;
        {
            #pragma unroll
            for (int k=0;k<4;k++) sl2[k]=pk2(sB[b*17+hoff+2*k], sB[b*17+hoff+2*k+1]);
            sl16 = sB[b*17+16];
        }
        float wv[17];
        #pragma unroll
        for (int d=0;d<17;d++) wv[d]=0.f;

        for (int a=0;a<16;a++){
            float na = nsv[a];
            #pragma unroll
            for (int c=0;c<17;c++){
                float t = na*ys[c];
                u64 t2 = bc2(t);
                const u64* wr = (const u64*)(Wb + (a*17+c)*18 + hoff);
                #pragma unroll
                for (int k=0;k<4;k++) fma2_(sl2[k], t2, wr[k]);
                sl16  += t*Wb[(a*17+c)*18+16];
                wv[c] += na*Vb[a*17+c];
            }
        }

        float vx=0.f, vy=0.f, vz=0.f;
        #pragma unroll
        for (int d=0;d<17;d++){
            float yx,yy,yz;
            if (d<16){ yx=g_accV[n*48+d*3+0]*fsc; yy=g_accV[n*48+d*3+1]*fsc; yz=g_accV[n*48+d*3+2]*fsc; }
            else     { yx=g_accAv[n*3+0]*fsc;     yy=g_accAv[n*3+1]*fsc;     yz=g_accAv[n*3+2]*fsc; }
            float t = nvx*yx+nvy*yy+nvz*yz;
            u64 t2 = bc2(t);
            const u64* wr = (const u64*)(Wb + (272+d)*18 + hoff);
            #pragma unroll
            for (int k=0;k<4;k++) fma2_(sl2[k], t2, wr[k]);
            sl16 += t*Wb[(272+d)*18+16];
            vx += yx*wv[d]; vy += yy*wv[d]; vz += yz*wv[d];
        }
        float sc=0.f;
        #pragma unroll
        for (int c=0;c<17;c++) sc += ys[c]*Vb[272+c];
        vx += nvx*sc; vy += nvy*sc; vz += nvz*sc;

        float slh[8];
        #pragma unroll
        for (int k=0;k<4;k++) upk2(sl2[k], slh[2*k], slh[2*k+1]);

        float ex[9];
        if (h==0){
            ex[0] = sigmoidf_(slh[0]);
            #pragma unroll
            for (int k=1;k<8;k++) ex[k] = geluf_(slh[k]);
            ex[8] = 0.f;
        } else {
            #pragma unroll
            for (int k=0;k<8;k++) ex[k] = geluf_(slh[k]);
            ex[8] = geluf_(sl16);
        }
        float ot[9];
        #pragma unroll
        for (int k=0;k<9;k++) ot[k] = __shfl_xor_sync(0xffffffffu, ex[k], 1);

        float g;
        if (h==0){
            g = ex[0];
            #pragma unroll
            for (int k=0;k<7;k++) nsv[k]   = ex[k+1];
            #pragma unroll
            for (int k=0;k<8;k++) nsv[7+k] = ot[k];
            nsv[15] = ot[8];
        } else {
            g = ot[0];
            #pragma unroll
            for (int k=0;k<7;k++) nsv[k]   = ot[k+1];
            #pragma unroll
            for (int k=0;k<8;k++) nsv[7+k] = ex[k];
            nsv[15] = ex[8];
        }
        nvx = vx*g; nvy = vy*g; nvz = vz*g;
    }

    u64 out2[4];
    {
        const u64* gs2 = (const u64*)(g_s + n*16 + hoff);
        const u64* fb2 = (const u64*)(sFb + hoff);
        #pragma unroll
        for (int k=0;k<4;k++){ out2[k]=gs2[k]; fma2_(out2[k], bc2(1.0f), fb2[k]); }
    }
    #pragma unroll
    for (int a=0;a<16;a++){
        u64 na2 = bc2(nsv[a]);
        const u64* w2 = (const u64*)(sF + a*16 + hoff);
        #pragma unroll
        for (int k=0;k<4;k++) fma2_(out2[k], na2, w2[k]);
    }
    if (valid){
        u64* gs2w = (u64*)(g_s + n*16 + hoff);
        #pragma unroll
        for (int k=0;k<4;k++) gs2w[k]=out2[k];
        if (h==0){
            float fv = sFv[0];
            g_v[n*3+0] += nvx*fv;
            g_v[n*3+1] += nvy*fv;
            g_v[n*3+2] += nvz*fv;
        }
    }
}

// ---------------- launch ----------------
extern "C" void kernel_launch(void* const* d_in, const int* in_sizes, int n_in,
                              void* d_out, int out_size)
{
    const float* node_s   = (const float*)d_in[0];
    const float* node_p   = (const float*)d_in[1];
    const int*   senders  = (const int*)d_in[2];
    const int*   receivers= (const int*)d_in[3];
    const float* eWs0 = (const float*)d_in[4];
    const float* ebs0 = (const float*)d_in[5];
    const float* eWv0 = (const float*)d_in[6];
    const float* eWs1 = (const float*)d_in[7];
    const float* ebs1 = (const float*)d_in[8];
    const float* eWv1 = (const float*)d_in[9];
    const float* nWs  = (const float*)d_in[10];
    const float* nbs  = (const float*)d_in[11];
    const float* nWv  = (const float*)d_in[12];
    const float* fWs  = (const float*)d_in[13];
    const float* fbs  = (const float*)d_in[14];
    const float* fWv  = (const float*)d_in[15];

    init_kernel<<<(NN*16+255)/256,256>>>(node_s, node_p);
    count_kernel<<<(NE+255)/256,256>>>(receivers);
    scan_kernel<<<1,1024>>>();
    scatter_kernel<<<(NE+255)/256,256>>>(senders, receivers);

    for (int t=0;t<3;t++){
        zero_kernel<<<(NN*48+255)/256,256>>>();
        edge_kernel<<<NE/128,128>>>(
            eWs0 + t*34*32, ebs0 + t*32, eWv0 + t*34*16,
            eWs1 + t*32*32, ebs1 + t*32, eWv1 + t*32*16);
        node_kernel<<<(2*NN+255)/256,256>>>(
            nWs + t*2*289*17, nbs + t*2*17, nWv + t*2*289,
            fWs + t*256, fbs + t*16, fWv + t);
    }
    pack_kernel<<<(NN+255)/256,256>>>((float*)d_out);
}

// round 14
// speedup vs baseline: 6.5388x; 6.5388x over previous
#include <cuda_runtime.h>

#define NN 20000
#define NE 320000
#define SQRT3F 1.7320508075688772f
#define INV_NORM (1.0f/319999.0f)

typedef unsigned long long u64;

// ---------------- persistent device state (no allocs allowed) ----------------
__device__ __align__(16) float g_s[NN*16];      // node scalars
__device__ __align__(16) float g_v[NN*3];       // node vector (positions)
__device__ __align__(16) float g_accS[NN*16];   // aggregated scalar messages
__device__ __align__(16) float g_accV[NN*48];   // aggregated vector messages [16][3]
__device__ __align__(16) float g_accAv[NN*3];   // aggregated edge attr vectors
__device__ __align__(16) float g_PS[NN*48];     // per-node precomp: sender half (incl bias)
__device__ __align__(16) float g_PR[NN*48];     // per-node precomp: receiver half
__device__ int g_cnt_i[NN];                     // per-receiver edge counts
__device__ int g_row[NN+1];                     // CSR row offsets (receiver-sorted)
__device__ int g_fill[NN];                      // scatter cursors
__device__ int g_src[NE];                       // senders in receiver-sorted order
__device__ int g_dst[NE];                       // receivers in receiver-sorted order
__device__ float g_msg[(size_t)67*NE];          // channel-major message buffer (~86MB)

// ---------------- f32x2 packed-math helpers (sm_103a dual FMA pipe) ----------
__device__ __forceinline__ u64 pk2(float a, float b){ u64 r; asm("mov.b64 %0,{%1,%2};":"=l"(r):"f"(a),"f"(b)); return r; }
__device__ __forceinline__ u64 bc2(float a){ return pk2(a,a); }
__device__ __forceinline__ void upk2(u64 v, float&a, float&b){ asm("mov.b64 {%0,%1},%2;":"=f"(a),"=f"(b):"l"(v)); }
__device__ __forceinline__ void fma2_(u64&d, u64 a, u64 b){ asm("fma.rn.f32x2 %0,%1,%2,%0;":"+l"(d):"l"(a),"l"(b)); }
__device__ __forceinline__ u64 mul2_(u64 a, u64 b){ u64 r; asm("mul.rn.f32x2 %0,%1,%2;":"=l"(r):"l"(a),"l"(b)); return r; }

__device__ __forceinline__ float sigmoidf_(float x){
    return 1.0f/(1.0f+__expf(-x));
}
// jax.nn.gelu default (approximate=True)
__device__ __forceinline__ float geluf_(float x){
    float t = 0.7978845608028654f*(x + 0.044715f*x*x*x);
    float e = __expf(2.0f*t);
    float th = 1.0f - 2.0f/(e+1.0f);
    return 0.5f*x*(1.0f+th);
}

// ---------------- init / CSR build / pack ----------------
__global__ void init_kernel(const float* __restrict__ s_in, const float* __restrict__ v_in){
    int i = blockIdx.x*256 + threadIdx.x;
    if (i < NN*16) g_s[i] = s_in[i];
    if (i < NN*3)  g_v[i] = v_in[i];
    if (i < NN)    g_cnt_i[i] = 0;
}

__global__ void count_kernel(const int* __restrict__ receivers){
    int e = blockIdx.x*256 + threadIdx.x;
    if (e < NE) atomicAdd(&g_cnt_i[receivers[e]], 1);
}

__global__ void scan_kernel(){
    __shared__ int part[1024];
    int t = threadIdx.x;
    int base = t*20;
    int s = 0;
    if (base < NN){
        #pragma unroll
        for (int i=0;i<20;i++){ int n=base+i; if (n<NN) s += g_cnt_i[n]; }
    }
    part[t]=s; __syncthreads();
    for (int off=1;off<1024;off<<=1){
        int v = (t>=off)?part[t-off]:0;
        __syncthreads();
        part[t]+=v;
        __syncthreads();
    }
    int excl = (t==0)?0:part[t-1];
    if (base < NN){
        int run = excl;
        #pragma unroll
        for (int i=0;i<20;i++){
            int n=base+i;
            if (n<NN){ g_row[n]=run; g_fill[n]=run; run+=g_cnt_i[n]; }
        }
    }
    if (t==1023) g_row[NN]=part[1023];
}

__global__ void scatter_kernel(const int* __restrict__ senders, const int* __restrict__ receivers){
    int e = blockIdx.x*256 + threadIdx.x;
    if (e >= NE) return;
    int ri = receivers[e];
    int s = atomicAdd(&g_fill[ri], 1);
    g_src[s] = senders[e];
    g_dst[s] = ri;
}

__global__ void pack_kernel(float* __restrict__ out){
    int n = blockIdx.x*256 + threadIdx.x;
    if (n >= NN) return;
    #pragma unroll
    for (int p=0;p<16;p++) out[n*19+p] = g_s[n*16+p];
    out[n*19+16] = g_v[n*3+0];
    out[n*19+17] = g_v[n*3+1];
    out[n*19+18] = g_v[n*3+2];
}

// ---------------- per-step precompute: layer-1 node halves ----------------
// PS[n][0..31] = bias + sum_a s[n][a]*Ws0[a][q]     PS[n][32..47] = sum_a s[n][a]*Wv0[a][q]
// PR[n][0..31] =        sum_a s[n][a]*Ws0[16+a][q]  PR[n][32..47] = sum_a s[n][a]*Wv0[16+a][q]
__global__ void __launch_bounds__(128) pre_kernel(
    const float* __restrict__ Ws0, const float* __restrict__ bs0, const float* __restrict__ Wv0)
{
    __shared__ __align__(16) float sW[32*32];   // Ws0 rows 0..31
    __shared__ __align__(16) float sV[32*16];   // Wv0 rows 0..31
    __shared__ __align__(16) float sB[32];
    int tid = threadIdx.x;
    for (int i=tid;i<32*32;i+=128) sW[i]=Ws0[i];
    for (int i=tid;i<32*16;i+=128) sV[i]=Wv0[i];
    if (tid<32) sB[tid]=bs0[tid];
    __syncthreads();

    int id = blockIdx.x*128 + tid;
    if (id >= 2*NN) return;
    int half = (id >= NN) ? 1 : 0;
    int n = id - half*NN;

    const float* srow = g_s + n*16;
    u64 acc[16], accu[8];
    if (half==0){
        const u64* b2 = (const u64*)sB;
        #pragma unroll
        for (int k=0;k<16;k++) acc[k]=b2[k];
    } else {
        #pragma unroll
        for (int k=0;k<16;k++) acc[k]=0ull;
    }
    #pragma unroll
    for (int k=0;k<8;k++) accu[k]=0ull;

    #pragma unroll 4
    for (int a=0;a<16;a++){
        u64 xa = bc2(srow[a]);
        const u64* w = (const u64*)(sW + (half*16+a)*32);
        #pragma unroll
        for (int k=0;k<16;k++) fma2_(acc[k], xa, w[k]);
        const u64* v = (const u64*)(sV + (half*16+a)*16);
        #pragma unroll
        for (int k=0;k<8;k++) fma2_(accu[k], xa, v[k]);
    }
    u64* out = (u64*)((half ? g_PR : g_PS) + n*48);
    #pragma unroll
    for (int k=0;k<16;k++) out[k]=acc[k];
    #pragma unroll
    for (int k=0;k<8;k++)  out[16+k]=accu[k];
}

// ---------------- edge kernel: precomp layer-1 + full layer-2, coalesced message write ----------------
__global__ void __launch_bounds__(128) edge_kernel(
    const float* __restrict__ Ws0, const float* __restrict__ Wv0,
    const float* __restrict__ Ws1, const float* __restrict__ bs1, const float* __restrict__ Wv1)
{
    __shared__ __align__(16) float sWs1[32*32];
    __shared__ __align__(16) float sWv1[32*16];
    __shared__ __align__(16) float sbs1[32];
    __shared__ __align__(16) float sw32[32];    // Ws0 row 32 (dS)
    __shared__ __align__(16) float sw33[32];    // Ws0 row 33 (dR)
    __shared__ __align__(16) float svw32[16];   // Wv0 row 32 (v_s)
    __shared__ __align__(16) float svw33[16];   // Wv0 row 33 (v_r)
    int tid = threadIdx.x;
    for (int i=tid;i<32*32;i+=128) sWs1[i]=Ws1[i];
    for (int i=tid;i<32*16;i+=128) sWv1[i]=Wv1[i];
    if (tid<32){ sbs1[tid]=bs1[tid]; sw32[tid]=Ws0[32*32+tid]; sw33[tid]=Ws0[33*32+tid]; }
    if (tid<16){ svw32[tid]=Wv0[32*16+tid]; svw33[tid]=Wv0[33*16+tid]; }
    __syncthreads();

    int s = blockIdx.x*128 + tid;      // slot in receiver-sorted order (NE%128==0)
    int si = g_src[s], ri = g_dst[s];

    float vsx=g_v[si*3+0], vsy=g_v[si*3+1], vsz=g_v[si*3+2];
    float vrx=g_v[ri*3+0], vry=g_v[ri*3+1], vrz=g_v[ri*3+2];
    float rx=vsx-vrx, ry=vsy-vry, rz=vsz-vrz;
    float nrm = sqrtf(rx*rx+ry*ry+rz*rz) + 1e-8f;
    float kk0 = SQRT3F/nrm;
    float avx=kk0*rx, avy=kk0*ry, avz=kk0*rz;   // a_v = sqrt(3) * rhat
    float dS = vsx*avx+vsy*avy+vsz*avz;
    float dR = vrx*avx+vry*avy+vrz*avz;

    // ---- layer 1 from precomp: sl = PS[si]+PR[ri]+dS*w32+dR*w33 ; u = PSu+PRu ----
    float sl[32], u[16];
    {
        const float4* ps = (const float4*)(g_PS + si*48);
        const float4* pr = (const float4*)(g_PR + ri*48);
        #pragma unroll
        for (int j=0;j<8;j++){
            float4 a=ps[j], b=pr[j];
            sl[4*j+0]=a.x+b.x; sl[4*j+1]=a.y+b.y; sl[4*j+2]=a.z+b.z; sl[4*j+3]=a.w+b.w;
        }
        #pragma unroll
        for (int j=0;j<4;j++){
            float4 a=ps[8+j], b=pr[8+j];
            u[4*j+0]=a.x+b.x; u[4*j+1]=a.y+b.y; u[4*j+2]=a.z+b.z; u[4*j+3]=a.w+b.w;
        }
        #pragma unroll
        for (int q=0;q<32;q++) sl[q] += dS*sw32[q] + dR*sw33[q];
    }

    float ms[16], mvx[16], mvy[16], mvz[16];
    #pragma unroll
    for (int q=0;q<16;q++){
        float g   = sigmoidf_(sl[q]);
        float w32 = svw32[q], w33 = svw33[q];
        mvx[q] = (avx*u[q] + vsx*w32 + vrx*w33)*g;
        mvy[q] = (avy*u[q] + vsy*w32 + vry*w33)*g;
        mvz[q] = (avz*u[q] + vsz*w32 + vrz*w33)*g;
        ms[q]  = geluf_(sl[16+q]);
    }

    // ---- layer 2 (packed) ----
    u64 s22[16], u22[8];
    {
        const u64* b1 = (const u64*)sbs1;
        #pragma unroll
        for (int k=0;k<16;k++) s22[k]=b1[k];
        #pragma unroll
        for (int k=0;k<8;k++)  u22[k]=0ull;
    }
    #pragma unroll 2
    for (int p=0;p<16;p++){
        float m  = ms[p];
        float d2 = mvx[p]*avx + mvy[p]*avy + mvz[p]*avz;
        u64 m2 = bc2(m), dd = bc2(d2);
        const u64* w  = (const u64*)(sWs1 + p*32);
        const u64* wb = (const u64*)(sWs1 + (16+p)*32);
        #pragma unroll
        for (int k=0;k<16;k++){ fma2_(s22[k], m2, w[k]); fma2_(s22[k], dd, wb[k]); }
        const u64* v = (const u64*)(sWv1 + p*16);
        #pragma unroll
        for (int k=0;k<8;k++) fma2_(u22[k], m2, v[k]);
    }
    float s2[32];
    #pragma unroll
    for (int k=0;k<16;k++) upk2(s22[k], s2[2*k], s2[2*k+1]);

    // ---- vector output ----
    u64 vxa[8], vya[8], vza[8];
    {
        u64 ax2=bc2(avx), ay2=bc2(avy), az2=bc2(avz);
        #pragma unroll
        for (int k=0;k<8;k++){ vxa[k]=mul2_(ax2,u22[k]); vya[k]=mul2_(ay2,u22[k]); vza[k]=mul2_(az2,u22[k]); }
    }
    #pragma unroll 4
    for (int p=0;p<16;p++){
        u64 mx=bc2(mvx[p]), my=bc2(mvy[p]), mz=bc2(mvz[p]);
        const u64* w2 = (const u64*)(sWv1 + (16+p)*16);
        #pragma unroll
        for (int k=0;k<8;k++){ fma2_(vxa[k],mx,w2[k]); fma2_(vya[k],my,w2[k]); fma2_(vza[k],mz,w2[k]); }
    }

    // ---- coalesced message write: channel-major planes, slot index s ----
    float* mp = g_msg + s;
    #pragma unroll
    for (int k=0;k<8;k++){
        float g0 = sigmoidf_(s2[2*k]);
        float g1 = sigmoidf_(s2[2*k+1]);
        float x0,x1,y0,y1,z0,z1;
        upk2(vxa[k],x0,x1); upk2(vya[k],y0,y1); upk2(vza[k],z0,z1);
        mp[(size_t)(16+6*k+0)*NE] = x0*g0;
        mp[(size_t)(16+6*k+1)*NE] = y0*g0;
        mp[(size_t)(16+6*k+2)*NE] = z0*g0;
        mp[(size_t)(16+6*k+3)*NE] = x1*g1;
        mp[(size_t)(16+6*k+4)*NE] = y1*g1;
        mp[(size_t)(16+6*k+5)*NE] = z1*g1;
        mp[(size_t)(2*k+0)*NE]    = geluf_(s2[16+2*k]);
        mp[(size_t)(2*k+1)*NE]    = geluf_(s2[16+2*k+1]);
    }
    mp[(size_t)64*NE] = avx;
    mp[(size_t)65*NE] = avy;
    mp[(size_t)66*NE] = avz;
}

// ---------------- aggregation: contiguous per-node sums, 4-way MLP ----------------
__global__ void __launch_bounds__(256) agg_kernel(){
    int n = blockIdx.x*256 + threadIdx.x;
    int c = blockIdx.y;
    if (n >= NN) return;
    int a = g_row[n], b = g_row[n+1];
    const float* p = g_msg + (size_t)c*NE;
    float s0=0.f, s1=0.f, s2=0.f, s3=0.f;
    int i=a;
    for (; i+3<b; i+=4){ s0+=p[i]; s1+=p[i+1]; s2+=p[i+2]; s3+=p[i+3]; }
    for (; i<b; i++) s0+=p[i];
    float sum = (s0+s1)+(s2+s3);
    if (c < 16)      g_accS[n*16+c]      = sum;
    else if (c < 64) g_accV[n*48+(c-16)] = sum;
    else             g_accAv[n*3+(c-64)] = sum;
}

// ---------------- node kernel: thread-pair per node, channel-split ----------------
__global__ void __launch_bounds__(256) node_kernel(
    const float* __restrict__ nWs, const float* __restrict__ nbs, const float* __restrict__ nWv,
    const float* __restrict__ fWs, const float* __restrict__ fbs, const float* __restrict__ fWv)
{
    __shared__ __align__(16) float sW[2*289*18];
    __shared__ __align__(16) float sV[2*289];
    __shared__ __align__(16) float sB[2*17];
    __shared__ __align__(16) float sF[256];
    __shared__ __align__(16) float sFb[16];
    __shared__ float sFv[1];
    int tid = threadIdx.x;
    for (int i=tid;i<2*289*17;i+=256){
        int b = i/(289*17); int r = i - b*289*17; int p = r/17; int q = r - p*17;
        sW[b*289*18 + p*18 + q] = nWs[i];
    }
    for (int i=tid;i<2*289;i+=256) sV[i]=nWv[i];
    if (tid<34) sB[tid]=nbs[tid];
    if (tid<256) sF[tid]=fWs[tid];
    if (tid<16) sFb[tid]=fbs[tid];
    if (tid==0) sFv[0]=fWv[0];
    __syncthreads();

    int id = blockIdx.x*256 + tid;
    bool valid = (id < 2*NN);
    int n  = valid ? (id >> 1) : (NN-1);   // clamp: ghost threads compute but never store
    int h  = id & 1;

    int r0i = g_row[n], r1i = g_row[n+1];
    float cnt = (float)(r1i - r0i);
    float fsc = INV_NORM / fmaxf(cnt,1.0f);
    float ys[17];
    #pragma unroll
    for (int c=0;c<16;c++) ys[c] = g_accS[n*16+c]*fsc;
    ys[16] = (cnt>0.f) ? INV_NORM : 0.f;

    float nsv[16];
    #pragma unroll
    for (int a=0;a<16;a++) nsv[a]=g_s[n*16+a];
    float nvx=g_v[n*3+0], nvy=g_v[n*3+1], nvz=g_v[n*3+2];

    int hoff = 8*h;

    #pragma unroll 1
    for (int b=0;b<2;b++){
        const float* Wb = sW + b*289*18;
        const float* Vb = sV + b*289;
        u64 sl2[4];
        float sl16;
        {
            #pragma unroll
            for (int k=0;k<4;k++) sl2[k]=pk2(sB[b*17+hoff+2*k], sB[b*17+hoff+2*k+1]);
            sl16 = sB[b*17+16];
        }
        float wv[17];
        #pragma unroll
        for (int d=0;d<17;d++) wv[d]=0.f;

        for (int a=0;a<16;a++){
            float na = nsv[a];
            #pragma unroll
            for (int c=0;c<17;c++){
                float t = na*ys[c];
                u64 t2 = bc2(t);
                const u64* wr = (const u64*)(Wb + (a*17+c)*18 + hoff);
                #pragma unroll
                for (int k=0;k<4;k++) fma2_(sl2[k], t2, wr[k]);
                sl16  += t*Wb[(a*17+c)*18+16];
                wv[c] += na*Vb[a*17+c];
            }
        }

        float vx=0.f, vy=0.f, vz=0.f;
        #pragma unroll
        for (int d=0;d<17;d++){
            float yx,yy,yz;
            if (d<16){ yx=g_accV[n*48+d*3+0]*fsc; yy=g_accV[n*48+d*3+1]*fsc; yz=g_accV[n*48+d*3+2]*fsc; }
            else     { yx=g_accAv[n*3+0]*fsc;     yy=g_accAv[n*3+1]*fsc;     yz=g_accAv[n*3+2]*fsc; }
            float t = nvx*yx+nvy*yy+nvz*yz;
            u64 t2 = bc2(t);
            const u64* wr = (const u64*)(Wb + (272+d)*18 + hoff);
            #pragma unroll
            for (int k=0;k<4;k++) fma2_(sl2[k], t2, wr[k]);
            sl16 += t*Wb[(272+d)*18+16];
            vx += yx*wv[d]; vy += yy*wv[d]; vz += yz*wv[d];
        }
        float sc=0.f;
        #pragma unroll
        for (int c=0;c<17;c++) sc += ys[c]*Vb[272+c];
        vx += nvx*sc; vy += nvy*sc; vz += nvz*sc;

        float slh[8];
        #pragma unroll
        for (int k=0;k<4;k++) upk2(sl2[k], slh[2*k], slh[2*k+1]);

        float ex[9];
        if (h==0){
            ex[0] = sigmoidf_(slh[0]);
            #pragma unroll
            for (int k=1;k<8;k++) ex[k] = geluf_(slh[k]);
            ex[8] = 0.f;
        } else {
            #pragma unroll
            for (int k=0;k<8;k++) ex[k] = geluf_(slh[k]);
            ex[8] = geluf_(sl16);
        }
        float ot[9];
        #pragma unroll
        for (int k=0;k<9;k++) ot[k] = __shfl_xor_sync(0xffffffffu, ex[k], 1);

        float g;
        if (h==0){
            g = ex[0];
            #pragma unroll
            for (int k=0;k<7;k++) nsv[k]   = ex[k+1];
            #pragma unroll
            for (int k=0;k<8;k++) nsv[7+k] = ot[k];
            nsv[15] = ot[8];
        } else {
            g = ot[0];
            #pragma unroll
            for (int k=0;k<7;k++) nsv[k]   = ot[k+1];
            #pragma unroll
            for (int k=0;k<8;k++) nsv[7+k] = ex[k];
            nsv[15] = ex[8];
        }
        nvx = vx*g; nvy = vy*g; nvz = vz*g;
    }

    u64 out2[4];
    {
        const u64* gs2 = (const u64*)(g_s + n*16 + hoff);
        const u64* fb2 = (const u64*)(sFb + hoff);
        #pragma unroll
        for (int k=0;k<4;k++){ out2[k]=gs2[k]; fma2_(out2[k], bc2(1.0f), fb2[k]); }
    }
    #pragma unroll
    for (int a=0;a<16;a++){
        u64 na2 = bc2(nsv[a]);
        const u64* w2 = (const u64*)(sF + a*16 + hoff);
        #pragma unroll
        for (int k=0;k<4;k++) fma2_(out2[k], na2, w2[k]);
    }
    if (valid){
        u64* gs2w = (u64*)(g_s + n*16 + hoff);
        #pragma unroll
        for (int k=0;k<4;k++) gs2w[k]=out2[k];
        if (h==0){
            float fv = sFv[0];
            g_v[n*3+0] += nvx*fv;
            g_v[n*3+1] += nvy*fv;
            g_v[n*3+2] += nvz*fv;
        }
    }
}

// ---------------- launch ----------------
extern "C" void kernel_launch(void* const* d_in, const int* in_sizes, int n_in,
                              void* d_out, int out_size)
{
    const float* node_s   = (const float*)d_in[0];
    const float* node_p   = (const float*)d_in[1];
    const int*   senders  = (const int*)d_in[2];
    const int*   receivers= (const int*)d_in[3];
    const float* eWs0 = (const float*)d_in[4];
    const float* ebs0 = (const float*)d_in[5];
    const float* eWv0 = (const float*)d_in[6];
    const float* eWs1 = (const float*)d_in[7];
    const float* ebs1 = (const float*)d_in[8];
    const float* eWv1 = (const float*)d_in[9];
    const float* nWs  = (const float*)d_in[10];
    const float* nbs  = (const float*)d_in[11];
    const float* nWv  = (const float*)d_in[12];
    const float* fWs  = (const float*)d_in[13];
    const float* fbs  = (const float*)d_in[14];
    const float* fWv  = (const float*)d_in[15];

    init_kernel<<<(NN*16+255)/256,256>>>(node_s, node_p);
    count_kernel<<<(NE+255)/256,256>>>(receivers);
    scan_kernel<<<1,1024>>>();
    scatter_kernel<<<(NE+255)/256,256>>>(senders, receivers);

    for (int t=0;t<3;t++){
        pre_kernel<<<(2*NN+127)/128,128>>>(
            eWs0 + t*34*32, ebs0 + t*32, eWv0 + t*34*16);
        edge_kernel<<<NE/128,128>>>(
            eWs0 + t*34*32, eWv0 + t*34*16,
            eWs1 + t*32*32, ebs1 + t*32, eWv1 + t*32*16);
        agg_kernel<<<dim3((NN+255)/256, 67),256>>>();
        node_kernel<<<(2*NN+255)/256,256>>>(
            nWs + t*2*289*17, nbs + t*2*17, nWv + t*2*289,
            fWs + t*256, fbs + t*16, fWv + t);
    }
    pack_kernel<<<(NN+255)/256,256>>>((float*)d_out);
}